// round 1
// baseline (speedup 1.0000x reference)
#include <cuda_runtime.h>
#include <math.h>

#define Bc 4
#define Tc 256
#define Uc 128
#define Ec 512
#define Dc 640
#define Hc 512
#define Vc 640

// Scratch for projected enc/dec features (no cudaMalloc allowed).
__device__ float g_enc[Bc * Tc * Hc];   // [B*T, H] = [1024, 512]
__device__ float g_dec[Bc * Uc * Hc];   // [B*U, H] = [512, 512]

// ---------------------------------------------------------------------------
// Projection GEMM: C[M,N] = A[M,K] @ W[K,N] (+ bias). M,N % 64 == 0, K % 16 == 0.
// 64x64 tile, BK=16, 256 threads, 4x4 micro-tile.
// ---------------------------------------------------------------------------
__global__ __launch_bounds__(256) void proj_kernel(
    const float* __restrict__ A, const float* __restrict__ W,
    const float* __restrict__ bias, float* __restrict__ C,
    int M, int N, int K)
{
    __shared__ float As[16][64];
    __shared__ float Ws[16][64];
    int tid = threadIdx.x;
    int row0 = blockIdx.y * 64, col0 = blockIdx.x * 64;
    int tx = tid & 15, ty = tid >> 4;
    float acc[4][4] = {};

    for (int k0 = 0; k0 < K; k0 += 16) {
        #pragma unroll
        for (int i = 0; i < 4; i++) {
            int lin = i * 256 + tid;
            int r = lin >> 4, kk = lin & 15;
            As[kk][r] = A[(row0 + r) * K + k0 + kk];
        }
        #pragma unroll
        for (int i = 0; i < 4; i++) {
            int lin = i * 256 + tid;
            int kk = lin >> 6, cc = lin & 63;
            Ws[kk][cc] = W[(k0 + kk) * N + col0 + cc];
        }
        __syncthreads();
        #pragma unroll
        for (int kk = 0; kk < 16; kk++) {
            float a[4], b[4];
            #pragma unroll
            for (int i = 0; i < 4; i++) a[i] = As[kk][ty * 4 + i];
            #pragma unroll
            for (int j = 0; j < 4; j++) b[j] = Ws[kk][tx * 4 + j];
            #pragma unroll
            for (int i = 0; i < 4; i++)
                #pragma unroll
                for (int j = 0; j < 4; j++)
                    acc[i][j] += a[i] * b[j];
        }
        __syncthreads();
    }

    #pragma unroll
    for (int i = 0; i < 4; i++) {
        int r = row0 + ty * 4 + i;
        #pragma unroll
        for (int j = 0; j < 4; j++) {
            int c = col0 + tx * 4 + j;
            float v = acc[i][j];
            if (bias) v += bias[c];
            C[r * N + c] = v;
        }
    }
}

// ---------------------------------------------------------------------------
// Joint kernel: out[bt, u, v] = tanh(enc[bt,:] + dec[b,u,:]) @ W_out + b_out
// One block = one (b,t) x 128 u-rows x 128 v-cols. BK=16, 256 threads,
// 8x8 micro-tile, register prefetch of next K-chunk overlapped with FMAs.
// ---------------------------------------------------------------------------
__global__ __launch_bounds__(256, 2) void joint_kernel(
    const float* __restrict__ Wout, const float* __restrict__ bout,
    float* __restrict__ out)
{
    __shared__ float As[16][128];   // [k][u]
    __shared__ float Bs[16][128];   // [k][v]

    int tid = threadIdx.x;
    int bt = blockIdx.y;              // 0..1023 == b*T + t
    int v0 = blockIdx.x * 128;        // 0,128,...,512
    int b  = bt >> 8;                 // T = 256
    const float* encR = g_enc + (size_t)bt * Hc;
    const float* decB = g_dec + (size_t)b * Uc * Hc;
    int tx = tid & 15, ty = tid >> 4;

    float acc[8][8] = {};

    // Per-thread load-lane decode (2 float4 loads each for A-side and B-side).
    int uA[2], kA[2], kB[2], vB[2];
    #pragma unroll
    for (int i = 0; i < 2; i++) {
        int lin = i * 256 + tid;
        uA[i] = lin >> 2;             // 0..127  (u row)
        kA[i] = (lin & 3) * 4;        // 0,4,8,12
        kB[i] = lin >> 5;             // 0..15   (k row)
        vB[i] = (lin & 31) * 4;       // 0..124  (v col)
    }

    float4 dreg[2], ereg[2], wreg[2];
    // Prologue: load K-chunk 0.
    #pragma unroll
    for (int i = 0; i < 2; i++) {
        dreg[i] = *(const float4*)&decB[uA[i] * Hc + kA[i]];
        ereg[i] = *(const float4*)&encR[kA[i]];
        wreg[i] = *(const float4*)&Wout[kB[i] * Vc + v0 + vB[i]];
    }

    const int NK = Hc / 16;   // 32
    for (int kt = 0; kt < NK; kt++) {
        __syncthreads();   // previous compute finished reading smem
        #pragma unroll
        for (int i = 0; i < 2; i++) {
            float4 d = dreg[i], e = ereg[i];
            As[kA[i] + 0][uA[i]] = tanhf(d.x + e.x);
            As[kA[i] + 1][uA[i]] = tanhf(d.y + e.y);
            As[kA[i] + 2][uA[i]] = tanhf(d.z + e.z);
            As[kA[i] + 3][uA[i]] = tanhf(d.w + e.w);
            *(float4*)&Bs[kB[i]][vB[i]] = wreg[i];
        }
        __syncthreads();

        if (kt + 1 < NK) {   // prefetch next chunk; latency hidden by FMAs below
            int k0 = (kt + 1) * 16;
            #pragma unroll
            for (int i = 0; i < 2; i++) {
                dreg[i] = *(const float4*)&decB[uA[i] * Hc + k0 + kA[i]];
                ereg[i] = *(const float4*)&encR[k0 + kA[i]];
                wreg[i] = *(const float4*)&Wout[(k0 + kB[i]) * Vc + v0 + vB[i]];
            }
        }

        #pragma unroll
        for (int kk = 0; kk < 16; kk++) {
            float a[8], w[8];
            *(float4*)&a[0] = *(const float4*)&As[kk][ty * 8];
            *(float4*)&a[4] = *(const float4*)&As[kk][ty * 8 + 4];
            *(float4*)&w[0] = *(const float4*)&Bs[kk][tx * 8];
            *(float4*)&w[4] = *(const float4*)&Bs[kk][tx * 8 + 4];
            #pragma unroll
            for (int i = 0; i < 8; i++)
                #pragma unroll
                for (int j = 0; j < 8; j++)
                    acc[i][j] += a[i] * w[j];
        }
    }

    // Epilogue: add bias, store as float4 pairs.
    float bo[8];
    #pragma unroll
    for (int j = 0; j < 8; j++) bo[j] = bout[v0 + tx * 8 + j];
    #pragma unroll
    for (int i = 0; i < 8; i++) {
        int u = ty * 8 + i;
        float* orow = out + ((size_t)(bt * Uc + u)) * Vc + v0 + tx * 8;
        float4 r0, r1;
        r0.x = acc[i][0] + bo[0]; r0.y = acc[i][1] + bo[1];
        r0.z = acc[i][2] + bo[2]; r0.w = acc[i][3] + bo[3];
        r1.x = acc[i][4] + bo[4]; r1.y = acc[i][5] + bo[5];
        r1.z = acc[i][6] + bo[6]; r1.w = acc[i][7] + bo[7];
        *(float4*)&orow[0] = r0;
        *(float4*)&orow[4] = r1;
    }
}

extern "C" void kernel_launch(void* const* d_in, const int* in_sizes, int n_in,
                              void* d_out, int out_size)
{
    const float* enc_out = (const float*)d_in[0];
    const float* dec_out = (const float*)d_in[1];
    const float* W_enc   = (const float*)d_in[2];
    const float* b_enc   = (const float*)d_in[3];
    const float* W_dec   = (const float*)d_in[4];
    const float* W_out   = (const float*)d_in[5];
    const float* b_out   = (const float*)d_in[6];
    float* out = (float*)d_out;

    float* genc = nullptr;
    float* gdec = nullptr;
    cudaGetSymbolAddress((void**)&genc, g_enc);
    cudaGetSymbolAddress((void**)&gdec, g_dec);

    dim3 blk(256);
    // enc: [1024, 512] = enc_out[1024,512] @ W_enc[512,512] + b_enc
    proj_kernel<<<dim3(Hc / 64, (Bc * Tc) / 64), blk>>>(
        enc_out, W_enc, b_enc, genc, Bc * Tc, Hc, Ec);
    // dec: [512, 512] = dec_out[512,640] @ W_dec[640,512]
    proj_kernel<<<dim3(Hc / 64, (Bc * Uc) / 64), blk>>>(
        dec_out, W_dec, nullptr, gdec, Bc * Uc, Hc, Dc);
    // joint: [1024, 128, 640]
    joint_kernel<<<dim3(Vc / 128, Bc * Tc), blk>>>(W_out, b_out, out);
}

// round 3
// speedup vs baseline: 5.9823x; 5.9823x over previous
#include <cuda_runtime.h>
#include <cuda_fp16.h>
#include <math.h>
#include <stdint.h>

#define Bc 4
#define Tc 256
#define Uc 128
#define Ec 512
#define Dc 640
#define Hc 512
#define Vc 640

// Scratch (no cudaMalloc allowed).
__device__ float  g_enc[Bc * Tc * Hc];            // [B*T, H]
__device__ float  g_dec[Bc * Uc * Hc];            // [B*U, H]
__device__ __half g_Wt[Vc * Hc];                  // W_out^T fp16: [V, H]
__device__ __half g_X[(size_t)Bc * Tc * Uc * Hc]; // tanh(enc+dec) fp16: [B*T, U, H]

// ---------------------------------------------------------------------------
// Helpers (sm_80-era PTX only — no 'a'-gated instructions)
// ---------------------------------------------------------------------------
__device__ __forceinline__ uint32_t smem_u32(const void* p) {
    return (uint32_t)__cvta_generic_to_shared(p);
}
__device__ __forceinline__ void cp16(uint32_t dst, const void* src) {
    asm volatile("cp.async.cg.shared.global [%0], [%1], 16;"
                 :: "r"(dst), "l"(src) : "memory");
}
__device__ __forceinline__ void cp_commit() {
    asm volatile("cp.async.commit_group;" ::: "memory");
}
__device__ __forceinline__ void cp_wait0() {
    asm volatile("cp.async.wait_group 0;" ::: "memory");
}
__device__ __forceinline__ void ldmx4(uint32_t* r, uint32_t addr) {
    asm volatile("ldmatrix.sync.aligned.m8n8.x4.shared.b16 {%0,%1,%2,%3}, [%4];"
                 : "=r"(r[0]), "=r"(r[1]), "=r"(r[2]), "=r"(r[3]) : "r"(addr));
}
__device__ __forceinline__ void mma16816(float* d, const uint32_t* a,
                                         uint32_t b0, uint32_t b1) {
    asm volatile(
        "mma.sync.aligned.m16n8k16.row.col.f32.f16.f16.f32 "
        "{%0,%1,%2,%3}, {%4,%5,%6,%7}, {%8,%9}, {%0,%1,%2,%3};"
        : "+f"(d[0]), "+f"(d[1]), "+f"(d[2]), "+f"(d[3])
        : "r"(a[0]), "r"(a[1]), "r"(a[2]), "r"(a[3]), "r"(b0), "r"(b1));
}
__device__ __forceinline__ uint32_t pack2(float a, float b) {
    __half2 h = __floats2half2_rn(a, b);
    return *reinterpret_cast<uint32_t*>(&h);
}

// ---------------------------------------------------------------------------
// W convert+transpose: g_Wt[v][k] = (half)W_out[k][v]
// ---------------------------------------------------------------------------
__global__ void convert_w(const float* __restrict__ W) {
    int v = blockIdx.x;
    for (int k = threadIdx.x; k < Hc; k += 256)
        g_Wt[(size_t)v * Hc + k] = __float2half_rn(W[(size_t)k * Vc + v]);
}

// ---------------------------------------------------------------------------
// Projection GEMM: C[M,N] = A[M,K] @ W[K,N] (+bias). 64x64 tile, BK=16,
// register-prefetch double buffer.
// ---------------------------------------------------------------------------
__global__ __launch_bounds__(256, 2) void proj_kernel(
    const float* __restrict__ A, const float* __restrict__ W,
    const float* __restrict__ bias, float* __restrict__ C,
    int M, int N, int K)
{
    __shared__ float As[16][64];
    __shared__ float Ws[16][64];
    int tid = threadIdx.x;
    int row0 = blockIdx.y * 64, col0 = blockIdx.x * 64;
    int tx = tid & 15, ty = tid >> 4;
    float acc[4][4] = {};

    int rA = tid >> 2, kqA = (tid & 3) * 4;
    int kW = tid >> 4, cqW = (tid & 15) * 4;

    float4 areg = *(const float4*)&A[(row0 + rA) * K + kqA];
    float4 wreg = *(const float4*)&W[kW * N + col0 + cqW];

    const int NK = K / 16;
    for (int kt = 0; kt < NK; kt++) {
        __syncthreads();
        As[kqA + 0][rA] = areg.x;
        As[kqA + 1][rA] = areg.y;
        As[kqA + 2][rA] = areg.z;
        As[kqA + 3][rA] = areg.w;
        *(float4*)&Ws[kW][cqW] = wreg;
        __syncthreads();
        if (kt + 1 < NK) {
            int k0 = (kt + 1) * 16;
            areg = *(const float4*)&A[(row0 + rA) * K + k0 + kqA];
            wreg = *(const float4*)&W[(k0 + kW) * N + col0 + cqW];
        }
        #pragma unroll
        for (int kk = 0; kk < 16; kk++) {
            float a[4], b[4];
            #pragma unroll
            for (int i = 0; i < 4; i++) a[i] = As[kk][ty * 4 + i];
            #pragma unroll
            for (int j = 0; j < 4; j++) b[j] = Ws[kk][tx * 4 + j];
            #pragma unroll
            for (int i = 0; i < 4; i++)
                #pragma unroll
                for (int j = 0; j < 4; j++)
                    acc[i][j] += a[i] * b[j];
        }
    }
    #pragma unroll
    for (int i = 0; i < 4; i++) {
        int r = row0 + ty * 4 + i;
        #pragma unroll
        for (int j = 0; j < 4; j++) {
            int c = col0 + tx * 4 + j;
            float v = acc[i][j];
            if (bias) v += bias[c];
            C[r * N + c] = v;
        }
    }
}

// ---------------------------------------------------------------------------
// X materialize: g_X[bt][u][k] = fp16(tanh(enc[bt][k] + dec[b][u][k]))
// ---------------------------------------------------------------------------
__global__ __launch_bounds__(256) void xmat_kernel() {
    int bt = blockIdx.x, b = bt >> 8, tid = threadIdx.x;
    const float* encR = g_enc + (size_t)bt * Hc;
    const float* decB = g_dec + (size_t)b * Uc * Hc;
    __half* Xo = g_X + (size_t)bt * (Uc * Hc);
    #pragma unroll 4
    for (int i = 0; i < 32; i++) {
        int idx = i * 256 + tid;        // 8192 vec8 units
        int u = idx >> 6;
        int k0 = (idx & 63) * 8;
        float4 d0 = *(const float4*)(decB + (size_t)u * Hc + k0);
        float4 d1 = *(const float4*)(decB + (size_t)u * Hc + k0 + 4);
        float4 e0 = *(const float4*)(encR + k0);
        float4 e1 = *(const float4*)(encR + k0 + 4);
        uint4 q;
        q.x = pack2(tanhf(d0.x + e0.x), tanhf(d0.y + e0.y));
        q.y = pack2(tanhf(d0.z + e0.z), tanhf(d0.w + e0.w));
        q.z = pack2(tanhf(d1.x + e1.x), tanhf(d1.y + e1.y));
        q.w = pack2(tanhf(d1.z + e1.z), tanhf(d1.w + e1.w));
        *(uint4*)(Xo + (size_t)u * Hc + k0) = q;
    }
}

// ---------------------------------------------------------------------------
// Joint GEMM (fp16 mma.sync): out[bt,u,v] = X[bt,u,:] @ Wt[v,:]^T + b_out[v]
// CTA: 128 u-rows x 128 v-cols, K-chunks of 64, double-buffered cp.async.
// 8 warps, warp tile 64x32 (2x4 grid), m16n8k16 frags, fp32 accum.
// SW128 XOR swizzle: off = r*128 + (c ^ ((r&7)<<4)), rows are 128B.
// ---------------------------------------------------------------------------
#define CH 64
#define NKT (Hc / CH)      // 8
#define TILE_B 16384       // one operand tile: 128 rows x 64 halfs = 16KB
#define GEMM_SMEM (4 * TILE_B)  // 64KB (2 bufs x {A,W})

__global__ __launch_bounds__(256, 2) void gemm_kernel(
    const float* __restrict__ bout, float* __restrict__ out)
{
    extern __shared__ char smem[];
    uint32_t sb = smem_u32(smem);
    int tid = threadIdx.x, l = tid & 31, w = tid >> 5;
    int bt = blockIdx.y, v0 = blockIdx.x * 128;
    const __half* Xs = g_X + (size_t)bt * (Uc * Hc);
    const __half* Wsrc = g_Wt + (size_t)v0 * Hc;
    int m0 = (w >> 2) * 64, n0 = (w & 3) * 32;

    // ldmatrix per-lane row/k decode
    int rowA = l & 15;                 // + m0 + mf*16
    int khA  = (l >> 4) * 16;          // k byte offset within 32B step
    int rowB = (l & 7) + ((l >> 4) << 3);  // + n0 + nb*16
    int khB  = ((l >> 3) & 1) * 16;

    float acc[4][4][4];
    #pragma unroll
    for (int i = 0; i < 4; i++)
        #pragma unroll
        for (int j = 0; j < 4; j++)
            #pragma unroll
            for (int q = 0; q < 4; q++) acc[i][j][q] = 0.f;

    // tile loader: 128 rows x 64 halfs, 16B units, swizzled
    #define LDTILE(dstb, src, k0)                                           \
        do {                                                                \
            _Pragma("unroll")                                               \
            for (int i_ = 0; i_ < 4; i_++) {                                \
                int idx_ = tid + i_ * 256;                                  \
                int r_ = idx_ >> 3, kg_ = idx_ & 7;                         \
                uint32_t off_ = r_ * 128 + ((kg_ * 16) ^ ((r_ & 7) << 4));  \
                cp16((dstb) + off_, (src) + (size_t)r_ * Hc + (k0) + kg_ * 8); \
            }                                                               \
        } while (0)

    LDTILE(sb, Xs, 0);
    LDTILE(sb + TILE_B, Wsrc, 0);
    cp_commit();

    for (int kt = 0; kt < NKT; kt++) {
        cp_wait0();
        __syncthreads();
        uint32_t Ab = sb + (kt & 1) * (2 * TILE_B);
        uint32_t Wb = Ab + TILE_B;
        if (kt + 1 < NKT) {
            uint32_t nbuf = sb + ((kt + 1) & 1) * (2 * TILE_B);
            LDTILE(nbuf, Xs, (kt + 1) * CH);
            LDTILE(nbuf + TILE_B, Wsrc, (kt + 1) * CH);
            cp_commit();
        }
        #pragma unroll
        for (int ks = 0; ks < 4; ks++) {
            uint32_t a[4][4], bb[2][4];
            #pragma unroll
            for (int mf = 0; mf < 4; mf++) {
                int r = m0 + mf * 16 + rowA;
                ldmx4(a[mf], Ab + r * 128 + ((ks * 32 + khA) ^ ((r & 7) << 4)));
            }
            #pragma unroll
            for (int nb = 0; nb < 2; nb++) {
                int r = n0 + nb * 16 + rowB;
                ldmx4(bb[nb], Wb + r * 128 + ((ks * 32 + khB) ^ ((r & 7) << 4)));
            }
            #pragma unroll
            for (int mf = 0; mf < 4; mf++)
                #pragma unroll
                for (int nf = 0; nf < 4; nf++)
                    mma16816(acc[mf][nf], a[mf],
                             bb[nf >> 1][2 * (nf & 1)], bb[nf >> 1][2 * (nf & 1) + 1]);
        }
    }

    // Epilogue: c frag lane mapping: rows gr, gr+8; cols 2*ct, 2*ct+1
    int gr = l >> 2, ct = l & 3;
    #pragma unroll
    for (int nf = 0; nf < 4; nf++) {
        int c = v0 + n0 + nf * 8 + 2 * ct;
        float b0v = bout[c], b1v = bout[c + 1];
        #pragma unroll
        for (int mf = 0; mf < 4; mf++) {
            int u = m0 + mf * 16 + gr;
            float* p = out + (size_t)bt * (Uc * Vc) + (size_t)u * Vc + c;
            float2 t0; t0.x = acc[mf][nf][0] + b0v; t0.y = acc[mf][nf][1] + b1v;
            float2 t1; t1.x = acc[mf][nf][2] + b0v; t1.y = acc[mf][nf][3] + b1v;
            *(float2*)p = t0;
            *(float2*)(p + 8 * Vc) = t1;
        }
    }
}

// ---------------------------------------------------------------------------
extern "C" void kernel_launch(void* const* d_in, const int* in_sizes, int n_in,
                              void* d_out, int out_size)
{
    const float* enc_out = (const float*)d_in[0];
    const float* dec_out = (const float*)d_in[1];
    const float* W_enc   = (const float*)d_in[2];
    const float* b_enc   = (const float*)d_in[3];
    const float* W_dec   = (const float*)d_in[4];
    const float* W_out   = (const float*)d_in[5];
    const float* b_out   = (const float*)d_in[6];
    float* out = (float*)d_out;

    float* genc = nullptr;
    float* gdec = nullptr;
    cudaGetSymbolAddress((void**)&genc, g_enc);
    cudaGetSymbolAddress((void**)&gdec, g_dec);

    cudaFuncSetAttribute(gemm_kernel,
                         cudaFuncAttributeMaxDynamicSharedMemorySize, GEMM_SMEM);

    convert_w<<<Vc, 256>>>(W_out);
    proj_kernel<<<dim3(Hc / 64, (Bc * Tc) / 64), 256>>>(
        enc_out, W_enc, b_enc, genc, Bc * Tc, Hc, Ec);
    proj_kernel<<<dim3(Hc / 64, (Bc * Uc) / 64), 256>>>(
        dec_out, W_dec, nullptr, gdec, Bc * Uc, Hc, Dc);
    xmat_kernel<<<Bc * Tc, 256>>>();
    gemm_kernel<<<dim3(Vc / 128, Bc * Tc), 256, GEMM_SMEM>>>(b_out, out);
}